// round 5
// baseline (speedup 1.0000x reference)
#include <cuda_runtime.h>

#define N_NODES 20000
#define BATCH   4
#define H_DIM   128
#define I_DIM   64
#define E_CAP   320000
#define NODEVEC (BATCH * H_DIM)          /* 512 floats per node, [b][h] */
#define BNH     (BATCH * N_NODES * H_DIM)

/* ---------------- device scratch (static, allocation-free) -------------- */
__device__ __align__(16) float g_hw[(size_t)N_NODES * NODEVEC];   /* (h*dn_src)@Wg, [n][b][h] */
__device__ __align__(16) float g_gh[(size_t)N_NODES * NODEVEC];   /* gcn output,   [n][b][h] */
__device__ int   g_outcnt[N_NODES];
__device__ int   g_incnt[N_NODES];
__device__ int   g_cursor[N_NODES];
__device__ int   g_off[N_NODES + 1];
__device__ int   g_csrc[E_CAP];
__device__ float g_dnsrc[N_NODES];
__device__ float g_dndst[N_NODES];
__device__ __align__(16) float g_gates[4 * BATCH * H_DIM];        /* [gate][b][h] */

/* ---------------- helpers ---------------------------------------------- */
__device__ __forceinline__ float sigf(float x) {
    return __fdividef(1.0f, 1.0f + __expf(-x));
}
__device__ __forceinline__ float tanh_fast(float x) {
    float t = __expf(-2.0f * x);
    return __fdividef(1.0f - t, 1.0f + t);
}

/* ---------------- K0: zero counters ------------------------------------ */
__global__ void k_zero() {
    int i = blockIdx.x * blockDim.x + threadIdx.x;
    if (i < N_NODES) { g_outcnt[i] = 0; g_incnt[i] = 0; g_cursor[i] = 0; }
}

/* ---------------- K1: degree histograms -------------------------------- */
__global__ void k_deg(const int* __restrict__ src, const int* __restrict__ dst, int E) {
    int e = blockIdx.x * blockDim.x + threadIdx.x;
    if (e < E) {
        atomicAdd(&g_outcnt[src[e]], 1);
        atomicAdd(&g_incnt[dst[e]], 1);
    }
}

/* ---------------- K2: single-block scan + degree norms ------------------ */
__global__ void k_scan() {
    const int T = 1024, CH = 20;          /* 1024*20 = 20480 >= N */
    __shared__ int part[T];
    int t = threadIdx.x;
    int base = t * CH;
    int s = 0;
    for (int i = 0; i < CH; i++) { int idx = base + i; if (idx < N_NODES) s += g_incnt[idx]; }
    part[t] = s;
    __syncthreads();
    for (int off = 1; off < T; off <<= 1) {
        int v = (t >= off) ? part[t - off] : 0;
        __syncthreads();
        part[t] += v;
        __syncthreads();
    }
    int run = (t == 0) ? 0 : part[t - 1];
    for (int i = 0; i < CH; i++) {
        int idx = base + i;
        if (idx < N_NODES) { g_off[idx] = run; run += g_incnt[idx]; }
    }
    if (t == T - 1) g_off[N_NODES] = run;
    for (int i = 0; i < CH; i++) {
        int idx = base + i;
        if (idx < N_NODES) {
            g_dndst[idx] = rsqrtf((float)max(g_incnt[idx], 1));
            g_dnsrc[idx] = rsqrtf((float)max(g_outcnt[idx], 1));
        }
    }
}

/* ---------------- K3: CSR fill (src ids grouped by dst) ----------------- */
__global__ void k_fill(const int* __restrict__ src, const int* __restrict__ dst, int E) {
    int e = blockIdx.x * blockDim.x + threadIdx.x;
    if (e < E) {
        int d = dst[e];
        int pos = atomicAdd(&g_cursor[d], 1);
        g_csrc[g_off[d] + pos] = src[e];
    }
}

/* ---------------- K4: tiny gate GEMVs  x@W + b  (4 gates) --------------- */
__global__ void k_gates(const float* __restrict__ x,
                        const float* __restrict__ Wi, const float* __restrict__ bi,
                        const float* __restrict__ Wf, const float* __restrict__ bf,
                        const float* __restrict__ Wo, const float* __restrict__ bo,
                        const float* __restrict__ Wc, const float* __restrict__ bc) {
    int tid = blockIdx.x * blockDim.x + threadIdx.x;
    if (tid >= 4 * BATCH * H_DIM) return;
    int g = tid / (BATCH * H_DIM);
    int b = (tid % (BATCH * H_DIM)) / H_DIM;
    int j = tid % H_DIM;
    const float* W; const float* bb;
    switch (g) {
        case 0:  W = Wi; bb = bi; break;
        case 1:  W = Wf; bb = bf; break;
        case 2:  W = Wo; bb = bo; break;
        default: W = Wc; bb = bc; break;
    }
    float s = bb[j];
    const float* xr = x + b * I_DIM;
#pragma unroll 8
    for (int k = 0; k < I_DIM; k++) s += xr[k] * W[k * H_DIM + j];
    g_gates[tid] = s;
}

/* ---------------- K5: hw[n][b][h] = (dn_src[n]*h_prev[b][n]) @ Wg ------- */
/* 64-row tiles, Wg streamed in 32-k chunks (24KB smem total).             */
__global__ void __launch_bounds__(256) k_mm(const float* __restrict__ hprev,
                                            const float* __restrict__ Wg) {
    __shared__ float Ws[32][H_DIM];   /* 16 KB */
    __shared__ float hs[64][32];      /* 8 KB  */
    __shared__ float rsc[64];

    int t  = threadIdx.x;
    int jq = t & 31;        /* owns output cols [4*jq, 4*jq+4) */
    int rg = t >> 5;        /* row group 0..7, 8 rows each     */
    int r0 = blockIdx.x * 64;

    if (t < 64) {
        int r = r0 + t;
        rsc[t] = g_dnsrc[r % N_NODES];
    }

    float4 acc[8];
#pragma unroll
    for (int r = 0; r < 8; r++) acc[r] = make_float4(0.f, 0.f, 0.f, 0.f);

    for (int kc = 0; kc < 4; kc++) {
        int k0 = kc * 32;
        __syncthreads();
        /* load Wg chunk: rows k0..k0+31, all 128 cols */
        {
            const float4* Wg4 = (const float4*)(Wg + (size_t)k0 * H_DIM);
            float4* Ws4 = (float4*)&Ws[0][0];
            for (int i = t; i < 1024; i += 256) Ws4[i] = Wg4[i];
        }
        /* load + scale h tile: 64 rows x 32 k */
        for (int i = t; i < 512; i += 256) {
            int rr = i >> 3;
            int cc = i & 7;
            float4 v = *(const float4*)(hprev + (size_t)(r0 + rr) * H_DIM + k0 + cc * 4);
            float sc = rsc[rr];
            v.x *= sc; v.y *= sc; v.z *= sc; v.w *= sc;
            *(float4*)&hs[rr][cc * 4] = v;
        }
        __syncthreads();

#pragma unroll
        for (int kk4 = 0; kk4 < 8; kk4++) {
            float4 hv[8];
#pragma unroll
            for (int r = 0; r < 8; r++)
                hv[r] = *(const float4*)&hs[rg * 8 + r][kk4 * 4];   /* broadcast */
#pragma unroll
            for (int sub = 0; sub < 4; sub++) {
                float4 w = *(const float4*)&Ws[kk4 * 4 + sub][jq * 4];
#pragma unroll
                for (int r = 0; r < 8; r++) {
                    float hvv = (sub == 0) ? hv[r].x : (sub == 1) ? hv[r].y
                              : (sub == 2) ? hv[r].z : hv[r].w;
                    acc[r].x += hvv * w.x;
                    acc[r].y += hvv * w.y;
                    acc[r].z += hvv * w.z;
                    acc[r].w += hvv * w.w;
                }
            }
        }
    }

#pragma unroll
    for (int r = 0; r < 8; r++) {
        int row = r0 + rg * 8 + r;
        int b = row / N_NODES;
        int n = row % N_NODES;
        *(float4*)&g_hw[(size_t)n * NODEVEC + b * H_DIM + jq * 4] = acc[r];
    }
}

/* ---------------- K6: gh[n] = dn_dst[n] * sum_{e in(n)} hw[src] + bg ---- */
__global__ void __launch_bounds__(128) k_agg(const float* __restrict__ bg) {
    int n = blockIdx.x;
    int t = threadIdx.x;                 /* owns float4 at offset 4t of 512 */
    int start = g_off[n], end = g_off[n + 1];

    float4 a0 = make_float4(0.f, 0.f, 0.f, 0.f);
    float4 a1 = a0, a2 = a0, a3 = a0;

    int e = start;
    for (; e + 4 <= end; e += 4) {
        int s0 = g_csrc[e + 0];
        int s1 = g_csrc[e + 1];
        int s2 = g_csrc[e + 2];
        int s3 = g_csrc[e + 3];
        float4 v0 = ((const float4*)&g_hw[(size_t)s0 * NODEVEC])[t];
        float4 v1 = ((const float4*)&g_hw[(size_t)s1 * NODEVEC])[t];
        float4 v2 = ((const float4*)&g_hw[(size_t)s2 * NODEVEC])[t];
        float4 v3 = ((const float4*)&g_hw[(size_t)s3 * NODEVEC])[t];
        a0.x += v0.x; a0.y += v0.y; a0.z += v0.z; a0.w += v0.w;
        a1.x += v1.x; a1.y += v1.y; a1.z += v1.z; a1.w += v1.w;
        a2.x += v2.x; a2.y += v2.y; a2.z += v2.z; a2.w += v2.w;
        a3.x += v3.x; a3.y += v3.y; a3.z += v3.z; a3.w += v3.w;
    }
    for (; e < end; e++) {
        int s = g_csrc[e];
        float4 v = ((const float4*)&g_hw[(size_t)s * NODEVEC])[t];
        a0.x += v.x; a0.y += v.y; a0.z += v.z; a0.w += v.w;
    }

    float dn = g_dndst[n];
    int hh = (t * 4) & (H_DIM - 1);
    float4 bgv = *(const float4*)&bg[hh];
    float4 r;
    r.x = (a0.x + a1.x + a2.x + a3.x) * dn + bgv.x;
    r.y = (a0.y + a1.y + a2.y + a3.y) * dn + bgv.y;
    r.z = (a0.z + a1.z + a2.z + a3.z) * dn + bgv.z;
    r.w = (a0.w + a1.w + a2.w + a3.w) * dn + bgv.w;
    ((float4*)&g_gh[(size_t)n * NODEVEC])[t] = r;
}

/* ---------------- K7: fused LSTM elementwise ---------------------------- */
__global__ void k_final(const float* __restrict__ cprev, float* __restrict__ out) {
    int i = blockIdx.x * blockDim.x + threadIdx.x;
    if (i >= BNH / 4) return;
    int p = i * 4;
    int b   = p / (N_NODES * H_DIM);
    int rem = p % (N_NODES * H_DIM);
    int n   = rem / H_DIM;
    int hh  = rem % H_DIM;

    float4 gv = *(const float4*)&g_gh[(size_t)n * NODEVEC + b * H_DIM + hh];
    float4 gi = *(const float4*)&g_gates[0 * BATCH * H_DIM + b * H_DIM + hh];
    float4 gf = *(const float4*)&g_gates[1 * BATCH * H_DIM + b * H_DIM + hh];
    float4 go = *(const float4*)&g_gates[2 * BATCH * H_DIM + b * H_DIM + hh];
    float4 gc = *(const float4*)&g_gates[3 * BATCH * H_DIM + b * H_DIM + hh];
    float4 cp = *(const float4*)&cprev[p];

    float4 ho, co;
#define LSTM_COMP(comp)                                              \
    {                                                                \
        float g  = gv.comp;                                          \
        float iv = sigf(gi.comp + g);                                \
        float fv = sigf(gf.comp + g);                                \
        float ov = sigf(go.comp + g);                                \
        float ct = tanh_fast(gc.comp + g);                           \
        float c  = fv * cp.comp + iv * ct;                           \
        co.comp  = c;                                                \
        ho.comp  = ov * tanh_fast(c);                                \
    }
    LSTM_COMP(x) LSTM_COMP(y) LSTM_COMP(z) LSTM_COMP(w)
#undef LSTM_COMP

    *(float4*)&out[p]       = ho;
    *(float4*)&out[BNH + p] = co;
}

/* ---------------- launch ------------------------------------------------ */
extern "C" void kernel_launch(void* const* d_in, const int* in_sizes, int n_in,
                              void* d_out, int out_size) {
    const float* x     = (const float*)d_in[0];
    const float* hprev = (const float*)d_in[1];
    const float* cprev = (const float*)d_in[2];
    const int*   src   = (const int*)  d_in[3];
    const int*   dst   = (const int*)  d_in[4];
    const float* Wi = (const float*)d_in[5];  const float* bi = (const float*)d_in[6];
    const float* Wf = (const float*)d_in[7];  const float* bf = (const float*)d_in[8];
    const float* Wo = (const float*)d_in[9];  const float* bo = (const float*)d_in[10];
    const float* Wc = (const float*)d_in[11]; const float* bc = (const float*)d_in[12];
    const float* Wg = (const float*)d_in[13]; const float* bg = (const float*)d_in[14];
    int E = in_sizes[3];
    float* out = (float*)d_out;

    k_zero <<<(N_NODES + 255) / 256, 256>>>();
    k_deg  <<<(E + 255) / 256, 256>>>(src, dst, E);
    k_scan <<<1, 1024>>>();
    k_fill <<<(E + 255) / 256, 256>>>(src, dst, E);
    k_gates<<<(4 * BATCH * H_DIM + 255) / 256, 256>>>(x, Wi, bi, Wf, bf, Wo, bo, Wc, bc);
    k_mm   <<<(BATCH * N_NODES) / 64, 256>>>(hprev, Wg);
    k_agg  <<<N_NODES, 128>>>(bg);
    k_final<<<(BNH / 4 + 255) / 256, 256>>>(cprev, out);
}

// round 6
// speedup vs baseline: 1.0512x; 1.0512x over previous
#include <cuda_runtime.h>

#define N_NODES 20000
#define BATCH   4
#define H_DIM   128
#define I_DIM   64
#define E_CAP   320000
#define NODEVEC (BATCH * H_DIM)          /* 512 floats per node, [b][h] */
#define BNH     (BATCH * N_NODES * H_DIM)

typedef unsigned long long ull;

/* ---------------- device scratch (static, allocation-free) -------------- */
__device__ __align__(16) float g_hw[(size_t)N_NODES * NODEVEC];   /* dn_src*(h@Wg), [n][b][h] */
__device__ int   g_outcnt[N_NODES];
__device__ int   g_incnt[N_NODES];
__device__ int   g_cursor[N_NODES];
__device__ int   g_off[N_NODES + 1];
__device__ int   g_csrc[E_CAP];
__device__ float g_dnsrc[N_NODES];
__device__ float g_dndst[N_NODES];
__device__ __align__(16) float g_gates[4 * BATCH * H_DIM];        /* [gate][b][h] */

/* ---------------- helpers ---------------------------------------------- */
__device__ __forceinline__ float sigf(float x) {
    return __fdividef(1.0f, 1.0f + __expf(-x));
}
__device__ __forceinline__ float tanh_fast(float x) {
    float t = __expf(-2.0f * x);
    return __fdividef(1.0f - t, 1.0f + t);
}
__device__ __forceinline__ ull fma2(ull a, ull b, ull c) {
    ull d;
    asm("fma.rn.f32x2 %0, %1, %2, %3;" : "=l"(d) : "l"(a), "l"(b), "l"(c));
    return d;
}
__device__ __forceinline__ ull pack2(float x) {
    ull d;
    asm("mov.b64 %0, {%1, %1};" : "=l"(d) : "f"(x));
    return d;
}
__device__ __forceinline__ float2 unpack2(ull v) {
    float2 f;
    asm("mov.b64 {%0, %1}, %2;" : "=f"(f.x), "=f"(f.y) : "l"(v));
    return f;
}

/* ---------------- K0: zero degree counters ------------------------------ */
__global__ void k_zero() {
    int i = blockIdx.x * blockDim.x + threadIdx.x;
    if (i < N_NODES) { g_outcnt[i] = 0; g_incnt[i] = 0; }
}

/* ---------------- K1: degree histograms (4 edges / thread) -------------- */
__global__ void k_deg(const int* __restrict__ src, const int* __restrict__ dst, int E) {
    int i = blockIdx.x * blockDim.x + threadIdx.x;
    int E4 = E >> 2;
    if (i < E4) {
        int4 s = ((const int4*)src)[i];
        int4 d = ((const int4*)dst)[i];
        atomicAdd(&g_outcnt[s.x], 1); atomicAdd(&g_outcnt[s.y], 1);
        atomicAdd(&g_outcnt[s.z], 1); atomicAdd(&g_outcnt[s.w], 1);
        atomicAdd(&g_incnt[d.x], 1);  atomicAdd(&g_incnt[d.y], 1);
        atomicAdd(&g_incnt[d.z], 1);  atomicAdd(&g_incnt[d.w], 1);
    }
    int e = E4 * 4 + i;
    if (e < E) { atomicAdd(&g_outcnt[src[e]], 1); atomicAdd(&g_incnt[dst[e]], 1); }
}

/* ---------------- K2: single-block scan + degree norms + cursor zero ---- */
__global__ void k_scan() {
    const int T = 1024, CH = 20;          /* 1024*20 = 20480 >= N */
    __shared__ int part[T];
    int t = threadIdx.x;
    int base = t * CH;
    int s = 0;
    for (int i = 0; i < CH; i++) { int idx = base + i; if (idx < N_NODES) s += g_incnt[idx]; }
    part[t] = s;
    __syncthreads();
    for (int off = 1; off < T; off <<= 1) {
        int v = (t >= off) ? part[t - off] : 0;
        __syncthreads();
        part[t] += v;
        __syncthreads();
    }
    int run = (t == 0) ? 0 : part[t - 1];
    for (int i = 0; i < CH; i++) {
        int idx = base + i;
        if (idx < N_NODES) { g_off[idx] = run; run += g_incnt[idx]; }
    }
    if (t == T - 1) g_off[N_NODES] = run;
    for (int i = 0; i < CH; i++) {
        int idx = base + i;
        if (idx < N_NODES) {
            g_dndst[idx]  = rsqrtf((float)max(g_incnt[idx], 1));
            g_dnsrc[idx]  = rsqrtf((float)max(g_outcnt[idx], 1));
            g_cursor[idx] = 0;
        }
    }
}

/* ---------------- K3: CSR fill (src ids grouped by dst, 4 edges/thread) - */
__global__ void k_fill(const int* __restrict__ src, const int* __restrict__ dst, int E) {
    int i = blockIdx.x * blockDim.x + threadIdx.x;
    int E4 = E >> 2;
    if (i < E4) {
        int4 s = ((const int4*)src)[i];
        int4 d = ((const int4*)dst)[i];
        g_csrc[g_off[d.x] + atomicAdd(&g_cursor[d.x], 1)] = s.x;
        g_csrc[g_off[d.y] + atomicAdd(&g_cursor[d.y], 1)] = s.y;
        g_csrc[g_off[d.z] + atomicAdd(&g_cursor[d.z], 1)] = s.z;
        g_csrc[g_off[d.w] + atomicAdd(&g_cursor[d.w], 1)] = s.w;
    }
    int e = E4 * 4 + i;
    if (e < E) {
        int d = dst[e];
        g_csrc[g_off[d] + atomicAdd(&g_cursor[d], 1)] = src[e];
    }
}

/* ---------------- K4: tiny gate GEMVs  x@W + b  (4 gates) --------------- */
__global__ void k_gates(const float* __restrict__ x,
                        const float* __restrict__ Wi, const float* __restrict__ bi,
                        const float* __restrict__ Wf, const float* __restrict__ bf,
                        const float* __restrict__ Wo, const float* __restrict__ bo,
                        const float* __restrict__ Wc, const float* __restrict__ bc) {
    int tid = blockIdx.x * blockDim.x + threadIdx.x;
    if (tid >= 4 * BATCH * H_DIM) return;
    int g = tid / (BATCH * H_DIM);
    int b = (tid % (BATCH * H_DIM)) / H_DIM;
    int j = tid % H_DIM;
    const float* W; const float* bb;
    switch (g) {
        case 0:  W = Wi; bb = bi; break;
        case 1:  W = Wf; bb = bf; break;
        case 2:  W = Wo; bb = bo; break;
        default: W = Wc; bb = bc; break;
    }
    float s = bb[j];
    const float* xr = x + b * I_DIM;
#pragma unroll 8
    for (int k = 0; k < I_DIM; k++) s += xr[k] * W[k * H_DIM + j];
    g_gates[tid] = s;
}

/* ---------------- K5: hw[n][b][h] = dn_src[n] * (h_prev[b][n] @ Wg) ----- */
/* 128-row tiles, Wg streamed in 32-k chunks, f32x2 packed FMAs.           */
/* 256 threads: 16 col-groups (8 cols) x 16 row-groups (8 rows).           */
__global__ void __launch_bounds__(256) k_mm(const float* __restrict__ hprev,
                                            const float* __restrict__ Wg) {
    __shared__ float Ws[32][H_DIM];   /* 16 KB */
    __shared__ float hs[128][32];     /* 16 KB */
    __shared__ float dsc[128];

    int t  = threadIdx.x;
    int jq = t & 15;        /* output cols [8*jq, 8*jq+8)  */
    int rg = t >> 4;        /* rows [8*rg, 8*rg+8) of tile */
    int r0 = blockIdx.x * 128;

    if (t < 128) {
        int row = r0 + t;
        dsc[t] = g_dnsrc[row % N_NODES];
    }

    ull acc[8][4];
#pragma unroll
    for (int r = 0; r < 8; r++)
#pragma unroll
        for (int p = 0; p < 4; p++) acc[r][p] = 0ull;

    for (int kc = 0; kc < 4; kc++) {
        int k0 = kc * 32;
        __syncthreads();
        /* Wg chunk: rows k0..k0+31, all 128 cols (linear float4 copy) */
        {
            const float4* Wg4 = (const float4*)(Wg + (size_t)k0 * H_DIM);
            float4* Ws4 = (float4*)&Ws[0][0];
#pragma unroll
            for (int i = 0; i < 4; i++) Ws4[t + i * 256] = Wg4[t + i * 256];
        }
        /* h tile: 128 rows x 32 k */
#pragma unroll
        for (int i = 0; i < 4; i++) {
            int idx = t + i * 256;
            int rr = idx >> 3;
            int cc = idx & 7;
            float4 v = *(const float4*)(hprev + (size_t)(r0 + rr) * H_DIM + k0 + cc * 4);
            *(float4*)&hs[rr][cc * 4] = v;
        }
        __syncthreads();

#pragma unroll 4
        for (int kk = 0; kk < 32; kk++) {
            float4 wa = *(const float4*)&Ws[kk][jq * 8];
            float4 wb = *(const float4*)&Ws[kk][jq * 8 + 4];
            ull w0 = ((const ull*)&wa)[0];
            ull w1 = ((const ull*)&wa)[1];
            ull w2 = ((const ull*)&wb)[0];
            ull w3 = ((const ull*)&wb)[1];
#pragma unroll
            for (int r = 0; r < 8; r++) {
                ull hb = pack2(hs[rg * 8 + r][kk]);   /* warp-broadcast LDS */
                acc[r][0] = fma2(hb, w0, acc[r][0]);
                acc[r][1] = fma2(hb, w1, acc[r][1]);
                acc[r][2] = fma2(hb, w2, acc[r][2]);
                acc[r][3] = fma2(hb, w3, acc[r][3]);
            }
        }
    }

#pragma unroll
    for (int r = 0; r < 8; r++) {
        int row = r0 + rg * 8 + r;
        float sc = dsc[rg * 8 + r];
        int b = row / N_NODES;
        int n = row - b * N_NODES;
        float2 p0 = unpack2(acc[r][0]);
        float2 p1 = unpack2(acc[r][1]);
        float2 p2 = unpack2(acc[r][2]);
        float2 p3 = unpack2(acc[r][3]);
        float4 o0 = make_float4(p0.x * sc, p0.y * sc, p1.x * sc, p1.y * sc);
        float4 o1 = make_float4(p2.x * sc, p2.y * sc, p3.x * sc, p3.y * sc);
        float* dstp = &g_hw[(size_t)n * NODEVEC + b * H_DIM + jq * 8];
        *(float4*)(dstp)     = o0;
        *(float4*)(dstp + 4) = o1;
    }
}

/* ---------------- K6: fused aggregation + LSTM epilogue ----------------- */
/* gh = dn_dst[n] * sum_{e in(n)} hw[src] + bg ; then LSTM gates.          */
__global__ void __launch_bounds__(128) k_aggf(const float* __restrict__ bg,
                                              const float* __restrict__ cprev,
                                              float* __restrict__ out) {
    int n = blockIdx.x;
    int t = threadIdx.x;                 /* owns float4 at offset 4t of 512 */
    int start = g_off[n], end = g_off[n + 1];

    float4 a0 = make_float4(0.f, 0.f, 0.f, 0.f);
    float4 a1 = a0, a2 = a0, a3 = a0;

    int e = start;
    for (; e + 4 <= end; e += 4) {
        int s0 = g_csrc[e + 0];
        int s1 = g_csrc[e + 1];
        int s2 = g_csrc[e + 2];
        int s3 = g_csrc[e + 3];
        float4 v0 = ((const float4*)&g_hw[(size_t)s0 * NODEVEC])[t];
        float4 v1 = ((const float4*)&g_hw[(size_t)s1 * NODEVEC])[t];
        float4 v2 = ((const float4*)&g_hw[(size_t)s2 * NODEVEC])[t];
        float4 v3 = ((const float4*)&g_hw[(size_t)s3 * NODEVEC])[t];
        a0.x += v0.x; a0.y += v0.y; a0.z += v0.z; a0.w += v0.w;
        a1.x += v1.x; a1.y += v1.y; a1.z += v1.z; a1.w += v1.w;
        a2.x += v2.x; a2.y += v2.y; a2.z += v2.z; a2.w += v2.w;
        a3.x += v3.x; a3.y += v3.y; a3.z += v3.z; a3.w += v3.w;
    }
    for (; e < end; e++) {
        int s = g_csrc[e];
        float4 v = ((const float4*)&g_hw[(size_t)s * NODEVEC])[t];
        a0.x += v.x; a0.y += v.y; a0.z += v.z; a0.w += v.w;
    }

    float dn = g_dndst[n];
    float4 bgv = ((const float4*)bg)[t & 31];
    float4 gv;
    gv.x = (a0.x + a1.x + a2.x + a3.x) * dn + bgv.x;
    gv.y = (a0.y + a1.y + a2.y + a3.y) * dn + bgv.y;
    gv.z = (a0.z + a1.z + a2.z + a3.z) * dn + bgv.z;
    gv.w = (a0.w + a1.w + a2.w + a3.w) * dn + bgv.w;

    /* LSTM epilogue: thread t -> batch b = t>>5, h offset (t&31)*4     */
    /* gates layout [gate][b][h]: float4 index = gate*128 + t           */
    const float4* G = (const float4*)g_gates;
    float4 gi = G[0 * 128 + t];
    float4 gf = G[1 * 128 + t];
    float4 go = G[2 * 128 + t];
    float4 gc = G[3 * 128 + t];

    int b = t >> 5;
    size_t p = ((size_t)b * N_NODES + n) * H_DIM + (t & 31) * 4;
    float4 cp = *(const float4*)&cprev[p];

    float4 ho, co;
#define LSTM_COMP(comp)                                              \
    {                                                                \
        float g  = gv.comp;                                          \
        float iv = sigf(gi.comp + g);                                \
        float fv = sigf(gf.comp + g);                                \
        float ov = sigf(go.comp + g);                                \
        float ct = tanh_fast(gc.comp + g);                           \
        float c  = fv * cp.comp + iv * ct;                           \
        co.comp  = c;                                                \
        ho.comp  = ov * tanh_fast(c);                                \
    }
    LSTM_COMP(x) LSTM_COMP(y) LSTM_COMP(z) LSTM_COMP(w)
#undef LSTM_COMP

    *(float4*)&out[p]       = ho;
    *(float4*)&out[BNH + p] = co;
}

/* ---------------- launch ------------------------------------------------ */
extern "C" void kernel_launch(void* const* d_in, const int* in_sizes, int n_in,
                              void* d_out, int out_size) {
    const float* x     = (const float*)d_in[0];
    const float* hprev = (const float*)d_in[1];
    const float* cprev = (const float*)d_in[2];
    const int*   src   = (const int*)  d_in[3];
    const int*   dst   = (const int*)  d_in[4];
    const float* Wi = (const float*)d_in[5];  const float* bi = (const float*)d_in[6];
    const float* Wf = (const float*)d_in[7];  const float* bf = (const float*)d_in[8];
    const float* Wo = (const float*)d_in[9];  const float* bo = (const float*)d_in[10];
    const float* Wc = (const float*)d_in[11]; const float* bc = (const float*)d_in[12];
    const float* Wg = (const float*)d_in[13]; const float* bg = (const float*)d_in[14];
    int E = in_sizes[3];
    float* out = (float*)d_out;

    int egrid = ((E >> 2) + 255) / 256;
    k_zero <<<(N_NODES + 255) / 256, 256>>>();
    k_deg  <<<egrid, 256>>>(src, dst, E);
    k_scan <<<1, 1024>>>();
    k_fill <<<egrid, 256>>>(src, dst, E);
    k_gates<<<(4 * BATCH * H_DIM + 255) / 256, 256>>>(x, Wi, bi, Wf, bf, Wo, bo, Wc, bc);
    k_mm   <<<(BATCH * N_NODES) / 128, 256>>>(hprev, Wg);
    k_aggf <<<N_NODES, 128>>>(bg, cprev, out);
}

// round 7
// speedup vs baseline: 1.4686x; 1.3971x over previous
#include <cuda_runtime.h>
#include <cuda_fp16.h>

#define N_NODES 20000
#define BATCH   4
#define H_DIM   128
#define I_DIM   64
#define E_CAP   320000
#define NODEVEC 512                       /* floats/halves per node, [b][h] */
#define BNH     (BATCH * N_NODES * H_DIM)
#define SCAN_BLKS 20

typedef unsigned long long ull;

/* ---------------- device scratch (static, allocation-free) -------------- */
__device__ __align__(16) __half g_hwh[(size_t)N_NODES * NODEVEC]; /* h@Wg (unscaled), fp16 */
__device__ int   g_outcnt[N_NODES];
__device__ int   g_incnt[N_NODES];
__device__ int   g_cursor[N_NODES];
__device__ int   g_off[N_NODES + 1];
__device__ __align__(8) int2 g_cedge[E_CAP];       /* {src, bits(dn_src[src])} */
__device__ float g_dnsrc[N_NODES];
__device__ float g_dndst[N_NODES];
__device__ int   g_bsum[SCAN_BLKS];
__device__ int   g_bpre[SCAN_BLKS + 1];
__device__ int   g_flagA, g_flagB;
__device__ __align__(16) float g_gates[4 * BATCH * H_DIM];        /* [gate][b][h] */

/* ---------------- helpers ---------------------------------------------- */
__device__ __forceinline__ float tanh_hw(float x) {
    float y;
    asm("tanh.approx.f32 %0, %1;" : "=f"(y) : "f"(x));
    return y;
}
__device__ __forceinline__ float sig_hw(float x) {
    return fmaf(tanh_hw(0.5f * x), 0.5f, 0.5f);
}
__device__ __forceinline__ ull fma2(ull a, ull b, ull c) {
    ull d;
    asm("fma.rn.f32x2 %0, %1, %2, %3;" : "=l"(d) : "l"(a), "l"(b), "l"(c));
    return d;
}
__device__ __forceinline__ ull pack2(float x) {
    ull d;
    asm("mov.b64 %0, {%1, %1};" : "=l"(d) : "f"(x));
    return d;
}
__device__ __forceinline__ float2 unpack2(ull v) {
    float2 f;
    asm("mov.b64 {%0, %1}, %2;" : "=f"(f.x), "=f"(f.y) : "l"(v));
    return f;
}

/* ---------------- K0: zero counters + flags ----------------------------- */
__global__ void k_zero() {
    int i = blockIdx.x * blockDim.x + threadIdx.x;
    if (i < N_NODES) { g_outcnt[i] = 0; g_incnt[i] = 0; }
    if (i == 0) { g_flagA = 0; g_flagB = 0; }
}

/* ---------------- K1 (fat): deg || gates || mm --------------------------
   grid = 946 blocks x 256:
     bid < 626 : even -> mm tile bid/2 ; odd -> deg block (bid-1)/2
     626..937  : mm tile 313 + (bid-626)
     938..945  : gates block bid-938
------------------------------------------------------------------------- */
__global__ void __launch_bounds__(256) k_fat(
        const float* __restrict__ hprev, const float* __restrict__ Wg,
        const int* __restrict__ src, const int* __restrict__ dst, int E,
        const float* __restrict__ x,
        const float* __restrict__ Wi, const float* __restrict__ bi,
        const float* __restrict__ Wf, const float* __restrict__ bf,
        const float* __restrict__ Wo, const float* __restrict__ bo,
        const float* __restrict__ Wc, const float* __restrict__ bc) {
    int bid = blockIdx.x;
    int t = threadIdx.x;

    int role, rid;                 /* 0=mm 1=deg 2=gates */
    if (bid < 626) {
        if (bid & 1) { role = 1; rid = (bid - 1) >> 1; }
        else         { role = 0; rid = bid >> 1; }
    } else if (bid < 938) { role = 0; rid = 313 + (bid - 626); }
    else                  { role = 2; rid = bid - 938; }

    if (role == 1) {
        /* -------- degree histograms, 4 edges / thread -------- */
        int i = rid * 256 + t;
        int E4 = E >> 2;
        if (i < E4) {
            int4 s = ((const int4*)src)[i];
            int4 d = ((const int4*)dst)[i];
            atomicAdd(&g_outcnt[s.x], 1); atomicAdd(&g_outcnt[s.y], 1);
            atomicAdd(&g_outcnt[s.z], 1); atomicAdd(&g_outcnt[s.w], 1);
            atomicAdd(&g_incnt[d.x], 1);  atomicAdd(&g_incnt[d.y], 1);
            atomicAdd(&g_incnt[d.z], 1);  atomicAdd(&g_incnt[d.w], 1);
        }
        int e = E4 * 4 + i;
        if (e < E) { atomicAdd(&g_outcnt[src[e]], 1); atomicAdd(&g_incnt[dst[e]], 1); }
        return;
    }

    if (role == 2) {
        /* -------- tiny gate GEMVs  x@W + b -------- */
        int tid = rid * 256 + t;
        int g = tid / (BATCH * H_DIM);
        int b = (tid % (BATCH * H_DIM)) / H_DIM;
        int j = tid % H_DIM;
        const float* W; const float* bb;
        switch (g) {
            case 0:  W = Wi; bb = bi; break;
            case 1:  W = Wf; bb = bf; break;
            case 2:  W = Wo; bb = bo; break;
            default: W = Wc; bb = bc; break;
        }
        float s = bb[j];
        const float* xr = x + b * I_DIM;
#pragma unroll 8
        for (int k = 0; k < I_DIM; k++) s += xr[k] * W[k * H_DIM + j];
        g_gates[tid] = s;
        return;
    }

    /* -------- mm: hwh[row] = h_prev[row] @ Wg   (fp16 out, unscaled) ----- */
    {
        __shared__ float Ws[32][H_DIM];   /* 16 KB */
        __shared__ float hs[128][32];     /* 16 KB */

        int jq = t & 15;        /* output cols [8*jq, 8*jq+8)  */
        int rg = t >> 4;        /* rows [8*rg, 8*rg+8) of tile */
        int r0 = rid * 128;

        ull acc[8][4];
#pragma unroll
        for (int r = 0; r < 8; r++)
#pragma unroll
            for (int p = 0; p < 4; p++) acc[r][p] = 0ull;

        for (int kc = 0; kc < 4; kc++) {
            int k0 = kc * 32;
            __syncthreads();
            {
                const float4* Wg4 = (const float4*)(Wg + (size_t)k0 * H_DIM);
                float4* Ws4 = (float4*)&Ws[0][0];
#pragma unroll
                for (int i = 0; i < 4; i++) Ws4[t + i * 256] = Wg4[t + i * 256];
            }
#pragma unroll
            for (int i = 0; i < 4; i++) {
                int idx = t + i * 256;
                int rr = idx >> 3;
                int cc = idx & 7;
                float4 v = *(const float4*)(hprev + (size_t)(r0 + rr) * H_DIM + k0 + cc * 4);
                *(float4*)&hs[rr][cc * 4] = v;
            }
            __syncthreads();

#pragma unroll 4
            for (int kk = 0; kk < 32; kk++) {
                float4 wa = *(const float4*)&Ws[kk][jq * 8];
                float4 wb = *(const float4*)&Ws[kk][jq * 8 + 4];
                ull w0 = ((const ull*)&wa)[0];
                ull w1 = ((const ull*)&wa)[1];
                ull w2 = ((const ull*)&wb)[0];
                ull w3 = ((const ull*)&wb)[1];
#pragma unroll
                for (int r = 0; r < 8; r++) {
                    ull hb = pack2(hs[rg * 8 + r][kk]);
                    acc[r][0] = fma2(hb, w0, acc[r][0]);
                    acc[r][1] = fma2(hb, w1, acc[r][1]);
                    acc[r][2] = fma2(hb, w2, acc[r][2]);
                    acc[r][3] = fma2(hb, w3, acc[r][3]);
                }
            }
        }

#pragma unroll
        for (int r = 0; r < 8; r++) {
            int row = r0 + rg * 8 + r;
            int b = row / N_NODES;
            int n = row - b * N_NODES;
            float2 p0 = unpack2(acc[r][0]);
            float2 p1 = unpack2(acc[r][1]);
            float2 p2 = unpack2(acc[r][2]);
            float2 p3 = unpack2(acc[r][3]);
            __half2 h0 = __floats2half2_rn(p0.x, p0.y);
            __half2 h1 = __floats2half2_rn(p1.x, p1.y);
            __half2 h2 = __floats2half2_rn(p2.x, p2.y);
            __half2 h3 = __floats2half2_rn(p3.x, p3.y);
            uint4 st;
            st.x = reinterpret_cast<unsigned&>(h0);
            st.y = reinterpret_cast<unsigned&>(h1);
            st.z = reinterpret_cast<unsigned&>(h2);
            st.w = reinterpret_cast<unsigned&>(h3);
            *(uint4*)&g_hwh[(size_t)n * NODEVEC + b * H_DIM + jq * 8] = st;
        }
    }
}

/* ---------------- K2: fused 3-phase scan (20 co-resident blocks) -------- */
__global__ void __launch_bounds__(1024) k_scan() {
    __shared__ int sm[1024];
    int bid = blockIdx.x;
    int t = threadIdx.x;
    int idx = bid * 1024 + t;
    int cnt = (idx < N_NODES) ? g_incnt[idx] : 0;

    /* phase 1: block sum */
    sm[t] = cnt;
    __syncthreads();
#pragma unroll
    for (int s = 512; s; s >>= 1) {
        if (t < s) sm[t] += sm[t + s];
        __syncthreads();
    }
    if (t == 0) {
        g_bsum[bid] = sm[0];
        __threadfence();
        atomicAdd(&g_flagA, 1);
    }

    /* phase 2: block 0 scans the 20 partials */
    if (bid == 0 && t == 0) {
        while (*((volatile int*)&g_flagA) < SCAN_BLKS) { }
        __threadfence();
        int run = 0;
        for (int b = 0; b < SCAN_BLKS; b++) {
            g_bpre[b] = run;
            run += *((volatile int*)&g_bsum[b]);
        }
        g_off[N_NODES] = run;
        __threadfence();
        atomicExch(&g_flagB, 1);
    }
    if (t == 0) {
        while (*((volatile int*)&g_flagB) == 0) { }
    }
    __syncthreads();
    int base = *((volatile int*)&g_bpre[bid]);

    /* phase 3: intra-block inclusive scan (Hillis-Steele) */
    sm[t] = cnt;
    __syncthreads();
#pragma unroll
    for (int off = 1; off < 1024; off <<= 1) {
        int u = (t >= off) ? sm[t - off] : 0;
        __syncthreads();
        sm[t] += u;
        __syncthreads();
    }
    if (idx < N_NODES) {
        int incl = sm[t];
        g_off[idx]   = base + incl - cnt;
        g_dndst[idx] = rsqrtf((float)max(cnt, 1));
        g_dnsrc[idx] = rsqrtf((float)max(g_outcnt[idx], 1));
        g_cursor[idx] = 0;
    }
}

/* ---------------- K3: CSR fill ({src, dn_src bits} by dst) -------------- */
__global__ void k_fill(const int* __restrict__ src, const int* __restrict__ dst, int E) {
    int i = blockIdx.x * blockDim.x + threadIdx.x;
    int E4 = E >> 2;
    if (i < E4) {
        int4 s = ((const int4*)src)[i];
        int4 d = ((const int4*)dst)[i];
        int2 e0 = make_int2(s.x, __float_as_int(g_dnsrc[s.x]));
        int2 e1 = make_int2(s.y, __float_as_int(g_dnsrc[s.y]));
        int2 e2 = make_int2(s.z, __float_as_int(g_dnsrc[s.z]));
        int2 e3 = make_int2(s.w, __float_as_int(g_dnsrc[s.w]));
        g_cedge[g_off[d.x] + atomicAdd(&g_cursor[d.x], 1)] = e0;
        g_cedge[g_off[d.y] + atomicAdd(&g_cursor[d.y], 1)] = e1;
        g_cedge[g_off[d.z] + atomicAdd(&g_cursor[d.z], 1)] = e2;
        g_cedge[g_off[d.w] + atomicAdd(&g_cursor[d.w], 1)] = e3;
    }
    int e = E4 * 4 + i;
    if (e < E) {
        int d = dst[e];
        int s = src[e];
        g_cedge[g_off[d] + atomicAdd(&g_cursor[d], 1)] =
            make_int2(s, __float_as_int(g_dnsrc[s]));
    }
}

/* ---------------- K4: fused fp16 aggregation + LSTM epilogue ------------ */
__global__ void __launch_bounds__(128) k_aggf(const float* __restrict__ bg,
                                              const float* __restrict__ cprev,
                                              float* __restrict__ out) {
    int n = blockIdx.x;
    int t = threadIdx.x;                 /* owns 4 halves at offset 4t of 512 */
    int start = g_off[n], end = g_off[n + 1];

    float4 a0 = make_float4(0.f, 0.f, 0.f, 0.f);
    float4 a1 = a0, a2 = a0, a3 = a0;

    int e = start;
    for (; e + 4 <= end; e += 4) {
        int2 e0 = g_cedge[e + 0];
        int2 e1 = g_cedge[e + 1];
        int2 e2 = g_cedge[e + 2];
        int2 e3 = g_cedge[e + 3];
        uint2 v0 = ((const uint2*)(g_hwh + (size_t)e0.x * NODEVEC))[t];
        uint2 v1 = ((const uint2*)(g_hwh + (size_t)e1.x * NODEVEC))[t];
        uint2 v2 = ((const uint2*)(g_hwh + (size_t)e2.x * NODEVEC))[t];
        uint2 v3 = ((const uint2*)(g_hwh + (size_t)e3.x * NODEVEC))[t];
#define ACC_EDGE(A, V, EE)                                                     \
        {                                                                      \
            float sc = __int_as_float(EE.y);                                   \
            float2 f0 = __half22float2(reinterpret_cast<__half2&>(V.x));       \
            float2 f1 = __half22float2(reinterpret_cast<__half2&>(V.y));       \
            A.x = fmaf(f0.x, sc, A.x);                                         \
            A.y = fmaf(f0.y, sc, A.y);                                         \
            A.z = fmaf(f1.x, sc, A.z);                                         \
            A.w = fmaf(f1.y, sc, A.w);                                         \
        }
        ACC_EDGE(a0, v0, e0)
        ACC_EDGE(a1, v1, e1)
        ACC_EDGE(a2, v2, e2)
        ACC_EDGE(a3, v3, e3)
    }
    for (; e < end; e++) {
        int2 ed = g_cedge[e];
        uint2 v = ((const uint2*)(g_hwh + (size_t)ed.x * NODEVEC))[t];
        ACC_EDGE(a0, v, ed)
    }
#undef ACC_EDGE

    float dn = g_dndst[n];
    float4 bgv = ((const float4*)bg)[t & 31];
    float4 gv;
    gv.x = (a0.x + a1.x + a2.x + a3.x) * dn + bgv.x;
    gv.y = (a0.y + a1.y + a2.y + a3.y) * dn + bgv.y;
    gv.z = (a0.z + a1.z + a2.z + a3.z) * dn + bgv.z;
    gv.w = (a0.w + a1.w + a2.w + a3.w) * dn + bgv.w;

    const float4* G = (const float4*)g_gates;
    float4 gi = G[0 * 128 + t];
    float4 gf = G[1 * 128 + t];
    float4 go = G[2 * 128 + t];
    float4 gc = G[3 * 128 + t];

    int b = t >> 5;
    size_t p = ((size_t)b * N_NODES + n) * H_DIM + (t & 31) * 4;
    float4 cp = *(const float4*)&cprev[p];

    float4 ho, co;
#define LSTM_COMP(comp)                                              \
    {                                                                \
        float g  = gv.comp;                                          \
        float iv = sig_hw(gi.comp + g);                              \
        float fv = sig_hw(gf.comp + g);                              \
        float ov = sig_hw(go.comp + g);                              \
        float ct = tanh_hw(gc.comp + g);                             \
        float c  = fv * cp.comp + iv * ct;                           \
        co.comp  = c;                                                \
        ho.comp  = ov * tanh_hw(c);                                  \
    }
    LSTM_COMP(x) LSTM_COMP(y) LSTM_COMP(z) LSTM_COMP(w)
#undef LSTM_COMP

    *(float4*)&out[p]       = ho;
    *(float4*)&out[BNH + p] = co;
}

/* ---------------- launch ------------------------------------------------ */
extern "C" void kernel_launch(void* const* d_in, const int* in_sizes, int n_in,
                              void* d_out, int out_size) {
    const float* x     = (const float*)d_in[0];
    const float* hprev = (const float*)d_in[1];
    const float* cprev = (const float*)d_in[2];
    const int*   src   = (const int*)  d_in[3];
    const int*   dst   = (const int*)  d_in[4];
    const float* Wi = (const float*)d_in[5];  const float* bi = (const float*)d_in[6];
    const float* Wf = (const float*)d_in[7];  const float* bf = (const float*)d_in[8];
    const float* Wo = (const float*)d_in[9];  const float* bo = (const float*)d_in[10];
    const float* Wc = (const float*)d_in[11]; const float* bc = (const float*)d_in[12];
    const float* Wg = (const float*)d_in[13]; const float* bg = (const float*)d_in[14];
    int E = in_sizes[3];
    float* out = (float*)d_out;

    k_zero <<<(N_NODES + 255) / 256, 256>>>();
    k_fat  <<<946, 256>>>(hprev, Wg, src, dst, E, x,
                          Wi, bi, Wf, bf, Wo, bo, Wc, bc);
    k_scan <<<SCAN_BLKS, 1024>>>();
    k_fill <<<((E >> 2) + 255) / 256, 256>>>(src, dst, E);
    k_aggf <<<N_NODES, 128>>>(bg, cprev, out);
}

// round 9
// speedup vs baseline: 2.0360x; 1.3863x over previous
#include <cuda_runtime.h>
#include <cuda_fp16.h>
#include <cuda_bf16.h>
#include <mma.h>
#include <cstdint>

#define N_NODES 20000
#define BATCH   4
#define H_DIM   128
#define I_DIM   64
#define E_CAP   320000
#define NODEVEC 512                       /* halves per node, [b][h] */
#define BNH     (BATCH * N_NODES * H_DIM)
#define SCAN_BLKS 20
#define SA_STRIDE 136                     /* smem stride (elems), mult of 8 */
#define FAT_SMEM  (128 * SA_STRIDE * 4)   /* 69632 B: 2 bf16 tiles OR 1 f32 tile */

typedef unsigned long long ull;
using namespace nvcuda;

/* ---------------- device scratch (static, allocation-free) -------------- */
__device__ __align__(16) __half g_hwh[(size_t)N_NODES * NODEVEC]; /* h@Wg (unscaled), fp16 */
__device__ __align__(16) __nv_bfloat16 g_Bbf[H_DIM * H_DIM];      /* bf16(Wg), [k][n] row-major */
__device__ int   g_outcnt[N_NODES];
__device__ int   g_incnt[N_NODES];
__device__ int   g_cursor[N_NODES];
__device__ int   g_off[N_NODES + 1];
__device__ __align__(8) int2 g_cedge[E_CAP];       /* {src, bits(dn_src[src])} */
__device__ float g_dnsrc[N_NODES];
__device__ float g_dndst[N_NODES];
__device__ int   g_bsum[SCAN_BLKS];
__device__ int   g_bpre[SCAN_BLKS + 1];
__device__ int   g_flagA, g_flagB;
__device__ __align__(16) float g_gates[4 * BATCH * H_DIM];        /* [gate][b][h] */

/* ---------------- helpers ---------------------------------------------- */
__device__ __forceinline__ float tanh_hw(float x) {
    float y;
    asm("tanh.approx.f32 %0, %1;" : "=f"(y) : "f"(x));
    return y;
}
__device__ __forceinline__ float sig_hw(float x) {
    return fmaf(tanh_hw(0.5f * x), 0.5f, 0.5f);
}

/* ---------------- K0: zero counters + build bf16(Wg) -------------------- */
__global__ void k_zero(const float* __restrict__ Wg) {
    int i = blockIdx.x * blockDim.x + threadIdx.x;
    if (i < N_NODES) { g_outcnt[i] = 0; g_incnt[i] = 0; }
    if (i == 0) { g_flagA = 0; g_flagB = 0; }
    if (i < H_DIM * H_DIM) g_Bbf[i] = __float2bfloat16(Wg[i]);
}

/* ---------------- K1 (fat): deg || gates || mm(wmma bf16) ----------------
   256 threads/block. grid = 946:
     bid < 626 : even -> mm tile bid/2 ; odd -> deg block (bid-1)/2
     626..937  : mm tile 313 + (bid-626)
     938..945  : gates block bid-938
------------------------------------------------------------------------- */
__global__ void __launch_bounds__(256) k_fat(
        const float* __restrict__ hprev,
        const int* __restrict__ src, const int* __restrict__ dst, int E,
        const float* __restrict__ x,
        const float* __restrict__ Wi, const float* __restrict__ bi,
        const float* __restrict__ Wf, const float* __restrict__ bf,
        const float* __restrict__ Wo, const float* __restrict__ bo,
        const float* __restrict__ Wc, const float* __restrict__ bc) {
    extern __shared__ unsigned char dsm[];
    int bid = blockIdx.x;
    int t = threadIdx.x;

    int role, rid;                 /* 0=mm 1=deg 2=gates */
    if (bid < 626) {
        if (bid & 1) { role = 1; rid = (bid - 1) >> 1; }
        else         { role = 0; rid = bid >> 1; }
    } else if (bid < 938) { role = 0; rid = 313 + (bid - 626); }
    else                  { role = 2; rid = bid - 938; }

    if (role == 1) {
        /* -------- degree histograms, 4 edges / thread -------- */
        int i = rid * 256 + t;
        int E4 = E >> 2;
        if (i < E4) {
            int4 s = ((const int4*)src)[i];
            int4 d = ((const int4*)dst)[i];
            atomicAdd(&g_outcnt[s.x], 1); atomicAdd(&g_outcnt[s.y], 1);
            atomicAdd(&g_outcnt[s.z], 1); atomicAdd(&g_outcnt[s.w], 1);
            atomicAdd(&g_incnt[d.x], 1);  atomicAdd(&g_incnt[d.y], 1);
            atomicAdd(&g_incnt[d.z], 1);  atomicAdd(&g_incnt[d.w], 1);
        }
        int e = E4 * 4 + i;
        if (e < E) { atomicAdd(&g_outcnt[src[e]], 1); atomicAdd(&g_incnt[dst[e]], 1); }
        return;
    }

    if (role == 2) {
        /* -------- tiny gate GEMVs  x@W + b -------- */
        int tid = rid * 256 + t;
        int g = tid / (BATCH * H_DIM);
        int b = (tid % (BATCH * H_DIM)) / H_DIM;
        int j = tid % H_DIM;
        const float* W; const float* bb;
        switch (g) {
            case 0:  W = Wi; bb = bi; break;
            case 1:  W = Wf; bb = bf; break;
            case 2:  W = Wo; bb = bo; break;
            default: W = Wc; bb = bc; break;
        }
        float s = bb[j];
        const float* xr = x + b * I_DIM;
#pragma unroll 8
        for (int k = 0; k < I_DIM; k++) s += xr[k] * W[k * H_DIM + j];
        g_gates[tid] = s;
        return;
    }

    /* -------- mm: g_hwh[tile rows] = bf16(h_prev) @ bf16(Wg) via HMMA ---- */
    {
        __nv_bfloat16* sA = (__nv_bfloat16*)dsm;                  /* 128 x 136 */
        __nv_bfloat16* sB = sA + 128 * SA_STRIDE;                 /* 128 x 136 */
        float*         sC = (float*)dsm;                          /* reuse      */

        int w   = t >> 5;                    /* warp 0..7: rows [16w,16w+16) */
        int r0  = rid * 128;

        /* A tile: 128 rows x 128 k fp32 -> bf16, stride 136 */
        {
            const float4* h4 = (const float4*)hprev;
#pragma unroll
            for (int i = 0; i < 16; i++) {
                int idx = t + i * 256;       /* 4096 float4 */
                int row = idx >> 5;
                int kq  = idx & 31;
                float4 v = h4[(size_t)(r0 + row) * 32 + kq];
                __nv_bfloat162 b01 = __floats2bfloat162_rn(v.x, v.y);
                __nv_bfloat162 b23 = __floats2bfloat162_rn(v.z, v.w);
                uint2 st;
                st.x = reinterpret_cast<unsigned&>(b01);
                st.y = reinterpret_cast<unsigned&>(b23);
                *(uint2*)&sA[row * SA_STRIDE + kq * 4] = st;
            }
        }
        /* B tile: bf16(Wg) [k][n], global stride 128 -> smem stride 136 */
        {
            const uint2* gb = (const uint2*)g_Bbf;                /* 4096 x 4 bf16 */
#pragma unroll
            for (int i = 0; i < 16; i++) {
                int idx = t + i * 256;
                int row = idx >> 5;
                int c4  = idx & 31;
                *(uint2*)&sB[row * SA_STRIDE + c4 * 4] = gb[idx];
            }
        }
        __syncthreads();

        wmma::fragment<wmma::accumulator, 16, 16, 16, float> acc[8];
#pragma unroll
        for (int nc = 0; nc < 8; nc++) wmma::fill_fragment(acc[nc], 0.0f);

        wmma::fragment<wmma::matrix_a, 16, 16, 16, __nv_bfloat16, wmma::row_major> af;
        wmma::fragment<wmma::matrix_b, 16, 16, 16, __nv_bfloat16, wmma::row_major> bf_;
#pragma unroll
        for (int ks = 0; ks < 8; ks++) {
            wmma::load_matrix_sync(af, &sA[(w * 16) * SA_STRIDE + ks * 16], SA_STRIDE);
#pragma unroll
            for (int nc = 0; nc < 8; nc++) {
                wmma::load_matrix_sync(bf_, &sB[(ks * 16) * SA_STRIDE + nc * 16], SA_STRIDE);
                wmma::mma_sync(acc[nc], af, bf_, acc[nc]);
            }
        }
        __syncthreads();                    /* done reading sA/sB */

#pragma unroll
        for (int nc = 0; nc < 8; nc++)
            wmma::store_matrix_sync(&sC[(w * 16) * SA_STRIDE + nc * 16], acc[nc],
                                    SA_STRIDE, wmma::mem_row_major);
        __syncthreads();

        /* write out as fp16: thread t -> row t>>1, cols [(t&1)*64, +64) */
        {
            int row = t >> 1;
            int c0  = (t & 1) * 64;
            int m = r0 + row;
            int b = m / N_NODES;
            int n = m - b * N_NODES;
            __half* dstp = g_hwh + (size_t)n * NODEVEC + b * H_DIM + c0;
            const float* srcp = &sC[row * SA_STRIDE + c0];
#pragma unroll
            for (int q = 0; q < 8; q++) {
                float4 v0 = *(const float4*)&srcp[q * 8];
                float4 v1 = *(const float4*)&srcp[q * 8 + 4];
                __half2 h0 = __floats2half2_rn(v0.x, v0.y);
                __half2 h1 = __floats2half2_rn(v0.z, v0.w);
                __half2 h2 = __floats2half2_rn(v1.x, v1.y);
                __half2 h3 = __floats2half2_rn(v1.z, v1.w);
                uint4 st;
                st.x = reinterpret_cast<unsigned&>(h0);
                st.y = reinterpret_cast<unsigned&>(h1);
                st.z = reinterpret_cast<unsigned&>(h2);
                st.w = reinterpret_cast<unsigned&>(h3);
                *(uint4*)(dstp + q * 8) = st;
            }
        }
    }
}

/* ---------------- K2: fused 3-phase scan (20 co-resident blocks) -------- */
__global__ void __launch_bounds__(1024) k_scan() {
    __shared__ int sm[1024];
    int bid = blockIdx.x;
    int t = threadIdx.x;
    int idx = bid * 1024 + t;
    int cnt = (idx < N_NODES) ? g_incnt[idx] : 0;

    sm[t] = cnt;
    __syncthreads();
#pragma unroll
    for (int s = 512; s; s >>= 1) {
        if (t < s) sm[t] += sm[t + s];
        __syncthreads();
    }
    if (t == 0) {
        g_bsum[bid] = sm[0];
        __threadfence();
        atomicAdd(&g_flagA, 1);
    }

    if (bid == 0 && t == 0) {
        while (*((volatile int*)&g_flagA) < SCAN_BLKS) { }
        __threadfence();
        int run = 0;
        for (int b = 0; b < SCAN_BLKS; b++) {
            g_bpre[b] = run;
            run += *((volatile int*)&g_bsum[b]);
        }
        g_off[N_NODES] = run;
        __threadfence();
        atomicExch(&g_flagB, 1);
    }
    if (t == 0) {
        while (*((volatile int*)&g_flagB) == 0) { }
    }
    __syncthreads();
    int base = *((volatile int*)&g_bpre[bid]);

    sm[t] = cnt;
    __syncthreads();
#pragma unroll
    for (int off = 1; off < 1024; off <<= 1) {
        int u = (t >= off) ? sm[t - off] : 0;
        __syncthreads();
        sm[t] += u;
        __syncthreads();
    }
    if (idx < N_NODES) {
        int incl = sm[t];
        g_off[idx]    = base + incl - cnt;
        g_dndst[idx]  = rsqrtf((float)max(cnt, 1));
        g_dnsrc[idx]  = rsqrtf((float)max(g_outcnt[idx], 1));
        g_cursor[idx] = 0;
    }
}

/* ---------------- K3: CSR fill ({src, dn_src bits} by dst) -------------- */
__global__ void k_fill(const int* __restrict__ src, const int* __restrict__ dst, int E) {
    int i = blockIdx.x * blockDim.x + threadIdx.x;
    int E4 = E >> 2;
    if (i < E4) {
        int4 s = ((const int4*)src)[i];
        int4 d = ((const int4*)dst)[i];
        int2 e0 = make_int2(s.x, __float_as_int(g_dnsrc[s.x]));
        int2 e1 = make_int2(s.y, __float_as_int(g_dnsrc[s.y]));
        int2 e2 = make_int2(s.z, __float_as_int(g_dnsrc[s.z]));
        int2 e3 = make_int2(s.w, __float_as_int(g_dnsrc[s.w]));
        g_cedge[g_off[d.x] + atomicAdd(&g_cursor[d.x], 1)] = e0;
        g_cedge[g_off[d.y] + atomicAdd(&g_cursor[d.y], 1)] = e1;
        g_cedge[g_off[d.z] + atomicAdd(&g_cursor[d.z], 1)] = e2;
        g_cedge[g_off[d.w] + atomicAdd(&g_cursor[d.w], 1)] = e3;
    }
    int e = E4 * 4 + i;
    if (e < E) {
        int d = dst[e];
        int s = src[e];
        g_cedge[g_off[d] + atomicAdd(&g_cursor[d], 1)] =
            make_int2(s, __float_as_int(g_dnsrc[s]));
    }
}

/* ---------------- K4: fused fp16 aggregation + LSTM epilogue ------------ */
__global__ void __launch_bounds__(128) k_aggf(const float* __restrict__ bg,
                                              const float* __restrict__ cprev,
                                              float* __restrict__ out) {
    int n = blockIdx.x;
    int t = threadIdx.x;                 /* owns 4 halves at offset 4t of 512 */
    int start = g_off[n], end = g_off[n + 1];

    float4 a0 = make_float4(0.f, 0.f, 0.f, 0.f);
    float4 a1 = a0, a2 = a0, a3 = a0;

    int e = start;
    for (; e + 4 <= end; e += 4) {
        int2 e0 = g_cedge[e + 0];
        int2 e1 = g_cedge[e + 1];
        int2 e2 = g_cedge[e + 2];
        int2 e3 = g_cedge[e + 3];
        uint2 v0 = ((const uint2*)(g_hwh + (size_t)e0.x * NODEVEC))[t];
        uint2 v1 = ((const uint2*)(g_hwh + (size_t)e1.x * NODEVEC))[t];
        uint2 v2 = ((const uint2*)(g_hwh + (size_t)e2.x * NODEVEC))[t];
        uint2 v3 = ((const uint2*)(g_hwh + (size_t)e3.x * NODEVEC))[t];
#define ACC_EDGE(A, V, EE)                                                     \
        {                                                                      \
            float sc = __int_as_float(EE.y);                                   \
            float2 f0 = __half22float2(reinterpret_cast<__half2&>(V.x));       \
            float2 f1 = __half22float2(reinterpret_cast<__half2&>(V.y));       \
            A.x = fmaf(f0.x, sc, A.x);                                         \
            A.y = fmaf(f0.y, sc, A.y);                                         \
            A.z = fmaf(f1.x, sc, A.z);                                         \
            A.w = fmaf(f1.y, sc, A.w);                                         \
        }
        ACC_EDGE(a0, v0, e0)
        ACC_EDGE(a1, v1, e1)
        ACC_EDGE(a2, v2, e2)
        ACC_EDGE(a3, v3, e3)
    }
    for (; e < end; e++) {
        int2 ed = g_cedge[e];
        uint2 v = ((const uint2*)(g_hwh + (size_t)ed.x * NODEVEC))[t];
        ACC_EDGE(a0, v, ed)
    }
#undef ACC_EDGE

    float dn = g_dndst[n];
    float4 bgv = ((const float4*)bg)[t & 31];
    float4 gv;
    gv.x = (a0.x + a1.x + a2.x + a3.x) * dn + bgv.x;
    gv.y = (a0.y + a1.y + a2.y + a3.y) * dn + bgv.y;
    gv.z = (a0.z + a1.z + a2.z + a3.z) * dn + bgv.z;
    gv.w = (a0.w + a1.w + a2.w + a3.w) * dn + bgv.w;

    const float4* G = (const float4*)g_gates;
    float4 gi = G[0 * 128 + t];
    float4 gf = G[1 * 128 + t];
    float4 go = G[2 * 128 + t];
    float4 gc = G[3 * 128 + t];

    int b = t >> 5;
    size_t p = ((size_t)b * N_NODES + n) * H_DIM + (t & 31) * 4;
    float4 cp = *(const float4*)&cprev[p];

    float4 ho, co;
#define LSTM_COMP(comp)                                              \
    {                                                                \
        float g  = gv.comp;                                          \
        float iv = sig_hw(gi.comp + g);                              \
        float fv = sig_hw(gf.comp + g);                              \
        float ov = sig_hw(go.comp + g);                              \
        float ct = tanh_hw(gc.comp + g);                             \
        float c  = fv * cp.comp + iv * ct;                           \
        co.comp  = c;                                                \
        ho.comp  = ov * tanh_hw(c);                                  \
    }
    LSTM_COMP(x) LSTM_COMP(y) LSTM_COMP(z) LSTM_COMP(w)
#undef LSTM_COMP

    *(float4*)&out[p]       = ho;
    *(float4*)&out[BNH + p] = co;
}

/* ---------------- launch ------------------------------------------------ */
extern "C" void kernel_launch(void* const* d_in, const int* in_sizes, int n_in,
                              void* d_out, int out_size) {
    const float* x     = (const float*)d_in[0];
    const float* hprev = (const float*)d_in[1];
    const float* cprev = (const float*)d_in[2];
    const int*   src   = (const int*)  d_in[3];
    const int*   dst   = (const int*)  d_in[4];
    const float* Wi = (const float*)d_in[5];  const float* bi = (const float*)d_in[6];
    const float* Wf = (const float*)d_in[7];  const float* bf = (const float*)d_in[8];
    const float* Wo = (const float*)d_in[9];  const float* bo = (const float*)d_in[10];
    const float* Wc = (const float*)d_in[11]; const float* bc = (const float*)d_in[12];
    const float* Wg = (const float*)d_in[13]; const float* bg = (const float*)d_in[14];
    int E = in_sizes[3];
    float* out = (float*)d_out;

    cudaFuncSetAttribute(k_fat, cudaFuncAttributeMaxDynamicSharedMemorySize, FAT_SMEM);

    k_zero <<<(N_NODES + 255) / 256, 256>>>(Wg);
    k_fat  <<<946, 256, FAT_SMEM>>>(hprev, src, dst, E, x,
                                    Wi, bi, Wf, bf, Wo, bo, Wc, bc);
    k_scan <<<SCAN_BLKS, 1024>>>();
    k_fill <<<((E >> 2) + 255) / 256, 256>>>(src, dst, E);
    k_aggf <<<N_NODES, 128>>>(bg, cprev, out);
}